// round 17
// baseline (speedup 1.0000x reference)
#include <cuda_runtime.h>
#include <math.h>

#define B_    64
#define T_    256
#define F_IN_ 2048
#define H_    1024
#define G3    3072

#define NB2   256            // scan blocks: each owns 4 j-indices
#define NT2   256            // 64 b x 4 jj
#define JPB   4
#define KC    64             // h staging chunk (k)
#define NCH   (H_ / KC)      // 16 chunks
#define WST   1028           // w slab row stride (floats), 16B-aligned, bank-shifted
#define HST   68             // h chunk row stride (floats)
#define SW_FLOATS (12 * WST)             // 12336
#define SH_FLOATS (2 * 64 * HST)         // 8704
#define SMEM2_BYTES ((SW_FLOATS + SH_FLOATS) * 4)   // 84160 B

// ---------------- scratch (static device allocations; no cudaMalloc) ----------
__device__ float g_emb[B_ * T_ * H_];
__device__ float g_gx [B_ * T_ * G3];
__device__ float g_h2 [2][B_ * H_];            // double-buffered hidden state
// barrier words on separate 128B L2 lines
__device__ unsigned int g_bar_count_pad[64];
__device__ volatile unsigned int g_bar_gen_pad[64];

__device__ __forceinline__ float fast_sigmoid(float x) {
    return 1.f / (1.f + __expf(-x));
}
__device__ __forceinline__ float fast_tanh(float x) {
    return 2.f / (1.f + __expf(-2.f * x)) - 1.f;
}

// ---------------- big SGEMM (double-buffered): C = A @ B^T + bias -------------
__global__ __launch_bounds__(256) void sgemm_nt_bias(
    const float* __restrict__ A, const float* __restrict__ Bm,
    const float* __restrict__ bias, float* __restrict__ C,
    int M, int N, int K)
{
    __shared__ float As[2][16][128 + 4];
    __shared__ float Bs[2][16][128 + 4];
    const int tid = threadIdx.x;
    const int bm = blockIdx.y * 128;
    const int bn = blockIdx.x * 128;
    const int tx = tid & 15;
    const int ty = tid >> 4;

    const int lr0 = tid >> 2;
    const int lc0 = (tid & 3) << 2;
    const int lr1 = (tid + 256) >> 2;
    const int lc1 = ((tid + 256) & 3) << 2;

    float acc[8][8];
#pragma unroll
    for (int i = 0; i < 8; i++)
#pragma unroll
        for (int j = 0; j < 8; j++) acc[i][j] = 0.f;

    {
        float4 va0 = *reinterpret_cast<const float4*>(&A[(size_t)(bm + lr0) * K + lc0]);
        float4 va1 = *reinterpret_cast<const float4*>(&A[(size_t)(bm + lr1) * K + lc1]);
        float4 vb0 = *reinterpret_cast<const float4*>(&Bm[(size_t)(bn + lr0) * K + lc0]);
        float4 vb1 = *reinterpret_cast<const float4*>(&Bm[(size_t)(bn + lr1) * K + lc1]);
        As[0][lc0 + 0][lr0] = va0.x; As[0][lc0 + 1][lr0] = va0.y; As[0][lc0 + 2][lr0] = va0.z; As[0][lc0 + 3][lr0] = va0.w;
        As[0][lc1 + 0][lr1] = va1.x; As[0][lc1 + 1][lr1] = va1.y; As[0][lc1 + 2][lr1] = va1.z; As[0][lc1 + 3][lr1] = va1.w;
        Bs[0][lc0 + 0][lr0] = vb0.x; Bs[0][lc0 + 1][lr0] = vb0.y; Bs[0][lc0 + 2][lr0] = vb0.z; Bs[0][lc0 + 3][lr0] = vb0.w;
        Bs[0][lc1 + 0][lr1] = vb1.x; Bs[0][lc1 + 1][lr1] = vb1.y; Bs[0][lc1 + 2][lr1] = vb1.z; Bs[0][lc1 + 3][lr1] = vb1.w;
    }
    __syncthreads();

    const int nch = K >> 4;
    for (int ch = 0; ch < nch; ch++) {
        const int cur = ch & 1, nxt = cur ^ 1;
        float4 pa0, pa1, pb0, pb1;
        const bool more = (ch + 1 < nch);
        if (more) {
            const int k0 = (ch + 1) << 4;
            pa0 = *reinterpret_cast<const float4*>(&A[(size_t)(bm + lr0) * K + k0 + lc0]);
            pa1 = *reinterpret_cast<const float4*>(&A[(size_t)(bm + lr1) * K + k0 + lc1]);
            pb0 = *reinterpret_cast<const float4*>(&Bm[(size_t)(bn + lr0) * K + k0 + lc0]);
            pb1 = *reinterpret_cast<const float4*>(&Bm[(size_t)(bn + lr1) * K + k0 + lc1]);
        }
#pragma unroll
        for (int k = 0; k < 16; k++) {
            float ar[8], br[8];
            *reinterpret_cast<float4*>(ar)     = *reinterpret_cast<const float4*>(&As[cur][k][ty * 8]);
            *reinterpret_cast<float4*>(ar + 4) = *reinterpret_cast<const float4*>(&As[cur][k][ty * 8 + 4]);
            *reinterpret_cast<float4*>(br)     = *reinterpret_cast<const float4*>(&Bs[cur][k][tx * 8]);
            *reinterpret_cast<float4*>(br + 4) = *reinterpret_cast<const float4*>(&Bs[cur][k][tx * 8 + 4]);
#pragma unroll
            for (int i = 0; i < 8; i++)
#pragma unroll
                for (int j = 0; j < 8; j++)
                    acc[i][j] += ar[i] * br[j];
        }
        if (more) {
            As[nxt][lc0 + 0][lr0] = pa0.x; As[nxt][lc0 + 1][lr0] = pa0.y; As[nxt][lc0 + 2][lr0] = pa0.z; As[nxt][lc0 + 3][lr0] = pa0.w;
            As[nxt][lc1 + 0][lr1] = pa1.x; As[nxt][lc1 + 1][lr1] = pa1.y; As[nxt][lc1 + 2][lr1] = pa1.z; As[nxt][lc1 + 3][lr1] = pa1.w;
            Bs[nxt][lc0 + 0][lr0] = pb0.x; Bs[nxt][lc0 + 1][lr0] = pb0.y; Bs[nxt][lc0 + 2][lr0] = pb0.z; Bs[nxt][lc0 + 3][lr0] = pb0.w;
            Bs[nxt][lc1 + 0][lr1] = pb1.x; Bs[nxt][lc1 + 1][lr1] = pb1.y; Bs[nxt][lc1 + 2][lr1] = pb1.z; Bs[nxt][lc1 + 3][lr1] = pb1.w;
        }
        __syncthreads();
    }

    const int row0 = bm + ty * 8;
    const int col0 = bn + tx * 8;
    float bb[8];
#pragma unroll
    for (int j = 0; j < 8; j++) bb[j] = bias[col0 + j];
#pragma unroll
    for (int i = 0; i < 8; i++) {
        float4 v0, v1;
        v0.x = acc[i][0] + bb[0]; v0.y = acc[i][1] + bb[1];
        v0.z = acc[i][2] + bb[2]; v0.w = acc[i][3] + bb[3];
        v1.x = acc[i][4] + bb[4]; v1.y = acc[i][5] + bb[5];
        v1.z = acc[i][6] + bb[6]; v1.w = acc[i][7] + bb[7];
        *reinterpret_cast<float4*>(&C[(size_t)(row0 + i) * N + col0])     = v0;
        *reinterpret_cast<float4*>(&C[(size_t)(row0 + i) * N + col0 + 4]) = v1;
    }
}

// ---------------- grid-wide barrier (padded lines, empty spin) ----------------
__device__ __forceinline__ void grid_barrier()
{
    __syncthreads();
    if (threadIdx.x == 0) {
        __threadfence();
        unsigned int gen = g_bar_gen_pad[0];
        unsigned int t = atomicAdd(&g_bar_count_pad[0], 1u);
        if (t == NB2 - 1) {
            g_bar_count_pad[0] = 0;
            __threadfence();
            g_bar_gen_pad[0] = gen + 1;
        } else {
            while (g_bar_gen_pad[0] == gen) { }
        }
        __threadfence();
    }
    __syncthreads();
}

// ---------------- persistent fused GRU scan: gate-major, no split-K -----------
// Block bid owns j0 = bid*4 .. +3. Smem: 12 w_hh rows {g*1024 + j0+jj} (48 KB,
// loaded once) + double-buffered h chunk [64 b][64 k] (2x17 KB). Per step:
// stage h chunks, full-K dots for (j,b), gate inline, ONE grid barrier.
__global__ void __launch_bounds__(NT2, 2) gru_scan_fused(
    const float* __restrict__ gx, const float* __restrict__ Whh,
    const float* __restrict__ b_hh, const int* __restrict__ lens,
    float* __restrict__ out)
{
    extern __shared__ float smem[];
    float* sW = smem;                  // [12][WST]
    float* sH = smem + SW_FLOATS;      // [2][64][HST]

    const int bid = blockIdx.x;
    const int tid = threadIdx.x;
    const int j0 = bid * JPB;
    const int jj = tid & 3;
    const int b  = tid >> 2;           // 0..63
    const int j  = j0 + jj;

    // ---- load w slab once: row r = gate*4+jj  <-  Whh[gate*1024 + j0 + jj] ----
#pragma unroll
    for (int i = 0; i < 12; i++) {
        const int idx = tid + i * NT2;         // 0..3071 float4 ids
        const int row = idx >> 8;              // 0..11
        const int c4  = (idx & 255) << 2;
        const int gate = row >> 2, jr = row & 3;
        const float4 w = __ldcg(reinterpret_cast<const float4*>(
            &Whh[(size_t)(gate * H_ + j0 + jr) * H_ + c4]));
        *reinterpret_cast<float4*>(&sW[row * WST + c4]) = w;
    }

    // per-thread constants
    const float bhr = b_hh[j];
    const float bhz = b_hh[H_ + j];
    const float bhn = b_hh[2 * H_ + j];
    const int   len = lens[b];

    // ---- h0 = 0 (buffer 0) ----
    for (int i = bid * NT2 + tid; i < B_ * H_; i += NB2 * NT2) g_h2[0][i] = 0.f;
    grid_barrier();

    const float* sWr = &sW[(0 * 4 + jj) * WST];
    const float* sWz = &sW[(1 * 4 + jj) * WST];
    const float* sWn = &sW[(2 * 4 + jj) * WST];

    for (int t = 0; t < T_; t++) {
        const int rd = t & 1, wr = rd ^ 1;
        const float* hsrc = g_h2[rd];

        // prefetch gate inputs early (hide DRAM latency behind FMA loop)
        const float* gxb = gx + ((size_t)b * T_ + t) * G3 + j;
        const float xr = __ldcg(gxb);
        const float xz = __ldcg(gxb + H_);
        const float xn = __ldcg(gxb + 2 * H_);
        const float hp = hsrc[b * H_ + j];

        // ---- stage chunk 0 ----
        {
#pragma unroll
            for (int i = 0; i < 4; i++) {
                const int idx = tid + i * NT2;     // 0..1023 float4 ids
                const int r   = idx >> 4;          // 0..63
                const int c4  = (idx & 15) << 2;   // 0..60
                const float4 a = __ldcg(reinterpret_cast<const float4*>(
                    &hsrc[r * H_ + c4]));
                *reinterpret_cast<float4*>(&sH[r * HST + c4]) = a;
            }
        }
        __syncthreads();

        float4 accr = make_float4(0.f, 0.f, 0.f, 0.f);
        float4 accz = accr, accn = accr;

#pragma unroll 1
        for (int c = 0; c < NCH; c++) {
            const int cur = c & 1, nxt = cur ^ 1;
            float4 pg[4];
            const bool more = (c + 1 < NCH);
            if (more) {
                const int kc = (c + 1) * KC;
#pragma unroll
                for (int i = 0; i < 4; i++) {
                    const int idx = tid + i * NT2;
                    const int r   = idx >> 4;
                    const int c4  = (idx & 15) << 2;
                    pg[i] = __ldcg(reinterpret_cast<const float4*>(
                        &hsrc[r * H_ + kc + c4]));
                }
            }
            const float* hrow = &sH[cur * 64 * HST + b * HST];
            const float* wr4  = sWr + c * KC;
            const float* wz4  = sWz + c * KC;
            const float* wn4  = sWn + c * KC;
#pragma unroll
            for (int k4 = 0; k4 < KC; k4 += 4) {
                const float4 h4 = *reinterpret_cast<const float4*>(&hrow[k4]);
                const float4 w1 = *reinterpret_cast<const float4*>(&wr4[k4]);
                const float4 w2 = *reinterpret_cast<const float4*>(&wz4[k4]);
                const float4 w3 = *reinterpret_cast<const float4*>(&wn4[k4]);
                accr.x += h4.x * w1.x; accr.y += h4.y * w1.y;
                accr.z += h4.z * w1.z; accr.w += h4.w * w1.w;
                accz.x += h4.x * w2.x; accz.y += h4.y * w2.y;
                accz.z += h4.z * w2.z; accz.w += h4.w * w2.w;
                accn.x += h4.x * w3.x; accn.y += h4.y * w3.y;
                accn.z += h4.z * w3.z; accn.w += h4.w * w3.w;
            }
            if (more) {
                __syncthreads();   // everyone done reading buf nxt from chunk c-1
#pragma unroll
                for (int i = 0; i < 4; i++) {
                    const int idx = tid + i * NT2;
                    const int r   = idx >> 4;
                    const int c4  = (idx & 15) << 2;
                    *reinterpret_cast<float4*>(&sH[nxt * 64 * HST + r * HST + c4]) = pg[i];
                }
                __syncthreads();
            }
        }

        // ---- gate (in registers) ----
        const float ghr = (accr.x + accr.y) + (accr.z + accr.w) + bhr;
        const float ghz = (accz.x + accz.y) + (accz.z + accz.w) + bhz;
        const float ghn = (accn.x + accn.y) + (accn.z + accn.w) + bhn;

        const float r = fast_sigmoid(xr + ghr);
        const float z = fast_sigmoid(xz + ghz);
        const float n = fast_tanh(xn + r * ghn);
        const float hnv = (1.f - z) * n + z * hp;
        const bool  m = t < len;

        const float hout = m ? hnv : hp;
        g_h2[wr][b * H_ + j] = hout;
        __stcg(&out[((size_t)b * T_ + t) * H_ + j], m ? hnv : 0.f);

        grid_barrier();
    }

    // hidden = output[:, T-1, :]
    for (int idx = bid * NT2 + tid; idx < B_ * H_; idx += NB2 * NT2) {
        const int bb = idx >> 10;
        const int jv = idx & 1023;
        out[(size_t)B_ * T_ * H_ + idx] =
            __ldcg(&out[((size_t)bb * T_ + (T_ - 1)) * H_ + jv]);
    }
}

// ---------------- launch ------------------------------------------------------
extern "C" void kernel_launch(void* const* d_in, const int* in_sizes, int n_in,
                              void* d_out, int out_size)
{
    const float* input = (const float*)d_in[0];
    const int*   lens  = (const int*)  d_in[1];
    const float* W_p   = (const float*)d_in[2];
    const float* b_p   = (const float*)d_in[3];
    const float* w_ih  = (const float*)d_in[4];
    const float* w_hh  = (const float*)d_in[5];
    const float* b_ih  = (const float*)d_in[6];
    const float* b_hh  = (const float*)d_in[7];
    float* out = (float*)d_out;

    float *emb, *gx;
    cudaGetSymbolAddress((void**)&emb, g_emb);
    cudaGetSymbolAddress((void**)&gx,  g_gx);

    // emb = input @ W_p^T + b_p          [16384 x 1024], K=2048
    dim3 g1(H_ / 128, (B_ * T_) / 128);
    sgemm_nt_bias<<<g1, 256>>>(input, W_p, b_p, emb, B_ * T_, H_, F_IN_);

    // gx = emb @ w_ih^T + b_ih           [16384 x 3072], K=1024
    dim3 g2(G3 / 128, (B_ * T_) / 128);
    sgemm_nt_bias<<<g2, 256>>>(emb, w_ih, b_ih, gx, B_ * T_, G3, H_);

    // persistent fused scan
    static int smem_set = 0;
    if (!smem_set) {
        cudaFuncSetAttribute(gru_scan_fused,
                             cudaFuncAttributeMaxDynamicSharedMemorySize, SMEM2_BYTES);
        smem_set = 1;
    }
    gru_scan_fused<<<NB2, NT2, SMEM2_BYTES>>>(gx, w_hh, b_hh, lens, out);
}